// round 5
// baseline (speedup 1.0000x reference)
#include <cuda_runtime.h>
#include <cuda_bf16.h>
#include <cstdint>

#define NB 8
#define SQ 2048
#define SK 2048
#define DQK 128
#define DV 128

#define SW 24     // bf16 stride, k-major 16-col tiles (48B rows, odd 16B units)
#define AW2 40    // bf16 stride for p tile rows, chunk 32 (80B = 5x16B odd)
#define BW 136    // bf16 stride for V tile rows (272B, 17x16B odd)

// bf16 hi/lo scratch
__device__ uint16_t g_qwh[NB * SQ * DQK], g_qwl[NB * SQ * DQK];
__device__ uint16_t g_kh[NB * SK * DQK],  g_kl[NB * SK * DQK];
__device__ uint16_t g_vh[NB * SK * DV],   g_vl[NB * SK * DV];
__device__ float    g_sum[NB * SQ];

// ---------------------------------------------------------------------------
struct HL { uint32_t h, l; };

__device__ __forceinline__ HL split2(float x, float y) {
    __nv_bfloat162 hh = __floats2bfloat162_rn(x, y);
    float hx = __bfloat162float(__low2bfloat16(hh));
    float hy = __bfloat162float(__high2bfloat16(hh));
    __nv_bfloat162 ll = __floats2bfloat162_rn(x - hx, y - hy);
    HL r;
    r.h = *reinterpret_cast<uint32_t*>(&hh);
    r.l = *reinterpret_cast<uint32_t*>(&ll);
    return r;
}

__device__ __forceinline__ void mma_bf16(float* c, const uint32_t* a,
                                         uint32_t b0, uint32_t b1) {
    asm volatile(
        "mma.sync.aligned.m16n8k16.row.col.f32.bf16.bf16.f32 "
        "{%0,%1,%2,%3}, {%4,%5,%6,%7}, {%8,%9}, {%0,%1,%2,%3};"
        : "+f"(c[0]), "+f"(c[1]), "+f"(c[2]), "+f"(c[3])
        : "r"(a[0]), "r"(a[1]), "r"(a[2]), "r"(a[3]), "r"(b0), "r"(b1));
}

__device__ __forceinline__ void ldsm_x4(uint32_t& r0, uint32_t& r1, uint32_t& r2,
                                        uint32_t& r3, uint32_t addr) {
    asm volatile("ldmatrix.sync.aligned.m8n8.x4.shared.b16 {%0,%1,%2,%3}, [%4];"
                 : "=r"(r0), "=r"(r1), "=r"(r2), "=r"(r3) : "r"(addr));
}

__device__ __forceinline__ void ldsm_x4_t(uint32_t& r0, uint32_t& r1, uint32_t& r2,
                                          uint32_t& r3, uint32_t addr) {
    asm volatile("ldmatrix.sync.aligned.m8n8.x4.trans.shared.b16 {%0,%1,%2,%3}, [%4];"
                 : "=r"(r0), "=r"(r1), "=r"(r2), "=r"(r3) : "r"(addr));
}

__device__ __forceinline__ void cpa16(uint32_t dst, const void* src) {
    asm volatile("cp.async.ca.shared.global [%0], [%1], 16;" :: "r"(dst), "l"(src));
}
#define CP_COMMIT() asm volatile("cp.async.commit_group;")
#define CP_WAIT0()  asm volatile("cp.async.wait_group 0;")

// ---------------------------------------------------------------------------
__global__ void zero_sum() {
    g_sum[(size_t)blockIdx.x * 256 + threadIdx.x] = 0.f;
}

// ---------------------------------------------------------------------------
// Prep: convert K and V fp32 -> bf16 hi/lo.
// ---------------------------------------------------------------------------
__global__ void prep_kv(const float* __restrict__ K, const float* __restrict__ V) {
    size_t i = ((size_t)blockIdx.x * 256 + threadIdx.x) * 8;
    float4 a0 = *(const float4*)&K[i];
    float4 a1 = *(const float4*)&K[i + 4];
    HL k0 = split2(a0.x, a0.y), k1 = split2(a0.z, a0.w);
    HL k2 = split2(a1.x, a1.y), k3 = split2(a1.z, a1.w);
    uint4 hv = {k0.h, k1.h, k2.h, k3.h};
    uint4 lv = {k0.l, k1.l, k2.l, k3.l};
    *(uint4*)&g_kh[i] = hv;
    *(uint4*)&g_kl[i] = lv;

    float4 b0 = *(const float4*)&V[i];
    float4 b1 = *(const float4*)&V[i + 4];
    HL v0 = split2(b0.x, b0.y), v1 = split2(b0.z, b0.w);
    HL v2 = split2(b1.x, b1.y), v3 = split2(b1.z, b1.w);
    uint4 hw = {v0.h, v1.h, v2.h, v3.h};
    uint4 lw = {v0.l, v1.l, v2.l, v3.l};
    *(uint4*)&g_vh[i] = hw;
    *(uint4*)&g_vl[i] = lw;
}

// ---------------------------------------------------------------------------
// Kernel 1: QW = Q @ W  (fp32 FFMA), writes bf16 hi/lo.
// ---------------------------------------------------------------------------
__global__ void qw_kernel(const float* __restrict__ Q, const float* __restrict__ W) {
    __shared__ float sAt[32][65];
    __shared__ float sB[32][128];

    const int tid = threadIdx.x;
    const int tx = tid & 15;
    const int ty = tid >> 4;
    const int m0 = blockIdx.x * 64;

    float acc[4][8];
#pragma unroll
    for (int i = 0; i < 4; i++)
#pragma unroll
        for (int j = 0; j < 8; j++) acc[i][j] = 0.f;

    for (int kk = 0; kk < DQK; kk += 32) {
#pragma unroll
        for (int r = 0; r < 8; r++) {
            int idx = tid + r * 256;
            int m = idx >> 5, k = idx & 31;
            sAt[k][m] = Q[(size_t)(m0 + m) * DQK + kk + k];
        }
#pragma unroll
        for (int r = 0; r < 16; r++) {
            int idx = tid + r * 256;
            int k = idx >> 7, n = idx & 127;
            sB[k][n] = W[(size_t)(kk + k) * DQK + n];
        }
        __syncthreads();

#pragma unroll
        for (int k = 0; k < 32; k++) {
            float a[4];
#pragma unroll
            for (int i = 0; i < 4; i++) a[i] = sAt[k][ty * 4 + i];
            float4 b0 = *(const float4*)&sB[k][tx * 8];
            float4 b1 = *(const float4*)&sB[k][tx * 8 + 4];
            float b[8] = {b0.x, b0.y, b0.z, b0.w, b1.x, b1.y, b1.z, b1.w};
#pragma unroll
            for (int i = 0; i < 4; i++)
#pragma unroll
                for (int j = 0; j < 8; j++) acc[i][j] = fmaf(a[i], b[j], acc[i][j]);
        }
        __syncthreads();
    }

#pragma unroll
    for (int i = 0; i < 4; i++) {
        size_t row = (size_t)(m0 + ty * 4 + i) * DQK + tx * 8;
        HL p0 = split2(acc[i][0], acc[i][1]), p1 = split2(acc[i][2], acc[i][3]);
        HL p2 = split2(acc[i][4], acc[i][5]), p3 = split2(acc[i][6], acc[i][7]);
        uint4 hv = {p0.h, p1.h, p2.h, p3.h};
        uint4 lv = {p0.l, p1.l, p2.l, p3.l};
        *(uint4*)&g_qwh[row] = hv;
        *(uint4*)&g_qwl[row] = lv;
    }
}

// ---------------------------------------------------------------------------
// Kernel 2: E = exp(QW @ K^T) via bf16x3 mma.sync; writes e to Wout and
// atomically accumulates per-row sums into g_sum.
// grid (SK/128, SQ/128, NB), block 256 = 8 warps (2x4). Tile 128x128, k=16.
// ---------------------------------------------------------------------------
__global__ void __launch_bounds__(256, 2)
score_kernel(float* __restrict__ Wout) {
    __shared__ __align__(16) uint16_t sA[2][2][128 * SW];
    __shared__ __align__(16) uint16_t sB[2][2][128 * SW];

    const int tid = threadIdx.x;
    const int warp = tid >> 5, lane = tid & 31;
    const int warpM = warp >> 2, warpN = warp & 3;
    const int gid = lane >> 2, tig = lane & 3;

    const int s0 = blockIdx.x * 128;
    const int q0 = blockIdx.y * 128;
    const int b = blockIdx.z;

    const size_t abase = ((size_t)b * SQ + q0) * DQK;
    const size_t bbase = ((size_t)b * SK + s0) * DQK;

    const int lrow = tid >> 1;
    const int lkb = (tid & 1) * 8;

    const int g = lane >> 3, lr = lane & 7;
    const uint32_t aoff = (uint32_t)(((((g & 1) * 8 + lr) * SW) + (g >> 1) * 8) * 2);
    const uint32_t boff = (uint32_t)((((warpN * 32 + (g >> 1) * 8 + lr) * SW) + (g & 1) * 8) * 2);

    const uint32_t sAbase = (uint32_t)__cvta_generic_to_shared(&sA[0][0][0]);
    const uint32_t sBbase = (uint32_t)__cvta_generic_to_shared(&sB[0][0][0]);
    const uint32_t HLSTRIDE = 128 * SW * 2;

    float c[4][4][4];
#pragma unroll
    for (int i = 0; i < 4; i++)
#pragma unroll
        for (int j = 0; j < 4; j++)
#pragma unroll
            for (int r = 0; r < 4; r++) c[i][j][r] = 0.f;

    uint4 ha = *(const uint4*)&g_qwh[abase + (size_t)lrow * DQK + lkb];
    uint4 la = *(const uint4*)&g_qwl[abase + (size_t)lrow * DQK + lkb];
    uint4 hb = *(const uint4*)&g_kh[bbase + (size_t)lrow * DQK + lkb];
    uint4 lb = *(const uint4*)&g_kl[bbase + (size_t)lrow * DQK + lkb];
    *(uint4*)&sA[0][0][lrow * SW + lkb] = ha;
    *(uint4*)&sA[0][1][lrow * SW + lkb] = la;
    *(uint4*)&sB[0][0][lrow * SW + lkb] = hb;
    *(uint4*)&sB[0][1][lrow * SW + lkb] = lb;
    __syncthreads();

    int buf = 0;
#pragma unroll 1
    for (int chunk = 0; chunk < 8; chunk++) {
        if (chunk < 7) {
            int kk = (chunk + 1) * 16;
            ha = *(const uint4*)&g_qwh[abase + (size_t)lrow * DQK + kk + lkb];
            la = *(const uint4*)&g_qwl[abase + (size_t)lrow * DQK + kk + lkb];
            hb = *(const uint4*)&g_kh[bbase + (size_t)lrow * DQK + kk + lkb];
            lb = *(const uint4*)&g_kl[bbase + (size_t)lrow * DQK + kk + lkb];
        }

        {
            const uint32_t bhi = sBbase + (uint32_t)buf * 2 * HLSTRIDE + boff;
            const uint32_t blo = bhi + HLSTRIDE;
            uint32_t bh[4][2], bl[4][2];
#pragma unroll
            for (int jj = 0; jj < 2; jj++) {
                ldsm_x4(bh[2 * jj][0], bh[2 * jj][1], bh[2 * jj + 1][0], bh[2 * jj + 1][1],
                        bhi + (uint32_t)(jj * 16 * SW * 2));
                ldsm_x4(bl[2 * jj][0], bl[2 * jj][1], bl[2 * jj + 1][0], bl[2 * jj + 1][1],
                        blo + (uint32_t)(jj * 16 * SW * 2));
            }
            const uint32_t ahi = sAbase + (uint32_t)buf * 2 * HLSTRIDE + aoff;
            const uint32_t alo = ahi + HLSTRIDE;
#pragma unroll
            for (int i = 0; i < 4; i++) {
                uint32_t arow = (uint32_t)((warpM * 64 + i * 16) * SW * 2);
                uint32_t ah[4], al[4];
                ldsm_x4(ah[0], ah[1], ah[2], ah[3], ahi + arow);
                ldsm_x4(al[0], al[1], al[2], al[3], alo + arow);
#pragma unroll
                for (int j = 0; j < 4; j++) {
                    mma_bf16(c[i][j], ah, bh[j][0], bh[j][1]);
                    mma_bf16(c[i][j], ah, bl[j][0], bl[j][1]);
                    mma_bf16(c[i][j], al, bh[j][0], bh[j][1]);
                }
            }
        }

        if (chunk < 7) {
            int nb = buf ^ 1;
            *(uint4*)&sA[nb][0][lrow * SW + lkb] = ha;
            *(uint4*)&sA[nb][1][lrow * SW + lkb] = la;
            *(uint4*)&sB[nb][0][lrow * SW + lkb] = hb;
            *(uint4*)&sB[nb][1][lrow * SW + lkb] = lb;
            __syncthreads();
        }
        buf ^= 1;
    }

    // epilogue: e = exp(s); row-partial sums -> atomicAdd; store e
#pragma unroll
    for (int i = 0; i < 4; i++) {
        int r1 = q0 + warpM * 64 + i * 16 + gid;
        float rs0 = 0.f, rs1 = 0.f;
#pragma unroll
        for (int j = 0; j < 4; j++) {
            c[i][j][0] = __expf(c[i][j][0]);
            c[i][j][1] = __expf(c[i][j][1]);
            c[i][j][2] = __expf(c[i][j][2]);
            c[i][j][3] = __expf(c[i][j][3]);
            rs0 += c[i][j][0] + c[i][j][1];
            rs1 += c[i][j][2] + c[i][j][3];
        }
        rs0 += __shfl_xor_sync(~0u, rs0, 1);
        rs0 += __shfl_xor_sync(~0u, rs0, 2);
        rs1 += __shfl_xor_sync(~0u, rs1, 1);
        rs1 += __shfl_xor_sync(~0u, rs1, 2);
        if (tig == 0) {
            atomicAdd(&g_sum[(size_t)b * SQ + r1], rs0);
            atomicAdd(&g_sum[(size_t)b * SQ + r1 + 8], rs1);
        }
#pragma unroll
        for (int j = 0; j < 4; j++) {
            int col = s0 + warpN * 32 + j * 8 + tig * 2;
            float2 v0 = {c[i][j][0], c[i][j][1]};
            float2 v1 = {c[i][j][2], c[i][j][3]};
            *(float2*)&Wout[((size_t)b * SQ + r1) * SK + col] = v0;
            *(float2*)&Wout[((size_t)b * SQ + r1 + 8) * SK + col] = v1;
        }
    }
}

// ---------------------------------------------------------------------------
// Kernel 3: fused normalize + PV, pipelined.
// grid (SQ/64, NB), block 256 = 8 warps (2 Mwarps x 4 Nwarps).
// s-chunk 32, double-buffered: V hi/lo via cp.async, e via LDG regs.
// p = e * inv written back to Wout; p split bf16 hi/lo -> MMA with V.
// ---------------------------------------------------------------------------
__global__ void __launch_bounds__(256, 2)
pv_fused(float* __restrict__ Wout, float* __restrict__ out) {
    __shared__ __align__(16) uint16_t sA[2][2][64 * AW2];  // p tile [q64][s32]
    __shared__ __align__(16) uint16_t sB[2][2][32 * BW];   // V tile [s32][v128]

    const int tid = threadIdx.x;
    const int warp = tid >> 5, lane = tid & 31;
    const int warpM = warp >> 2, warpN = warp & 3;
    const int gid = lane >> 2, tig = lane & 3;

    const int q0 = blockIdx.x * 64;
    const int b = blockIdx.y;

    // e/p: thread -> row tid>>2 (0..63), 8 cols at (tid&3)*8
    const int srow = tid >> 2;
    const int scol = (tid & 3) * 8;
    const float inv = 1.f / g_sum[(size_t)b * SQ + q0 + srow];
    float* Sp = Wout + ((size_t)b * SQ + q0 + srow) * SK;

    // V: thread -> row tid>>3 (0..31), 16 cols at (tid&7)*16
    const int vrow = tid >> 3;
    const int vcol = (tid & 7) * 16;
    const uint16_t* vh = g_vh + (size_t)b * SK * DV + (size_t)vrow * DV + vcol;
    const uint16_t* vl = g_vl + (size_t)b * SK * DV + (size_t)vrow * DV + vcol;

    const int g = lane >> 3, lr = lane & 7;
    const uint32_t aoff = (uint32_t)(((((g & 1) * 8 + lr) * AW2) + (g >> 1) * 8) * 2);
    const uint32_t btoff = (uint32_t)((((g & 1) * 8 + lr) * BW + (warpN * 32 + (g >> 1) * 8)) * 2);

    const uint32_t sAbase = (uint32_t)__cvta_generic_to_shared(&sA[0][0][0]);
    const uint32_t sBbase = (uint32_t)__cvta_generic_to_shared(&sB[0][0][0]);
    const uint32_t ABUF = 64 * AW2 * 2;   // bytes per (hl) array
    const uint32_t BBUF = 32 * BW * 2;

    // smem byte offsets for this thread's stores
    const uint32_t aSt = (uint32_t)((srow * AW2 + scol) * 2);
    const uint32_t bSt = (uint32_t)((vrow * BW + vcol) * 2);

    float c[2][4][4];
#pragma unroll
    for (int i = 0; i < 2; i++)
#pragma unroll
        for (int j = 0; j < 4; j++)
#pragma unroll
            for (int r = 0; r < 4; r++) c[i][j][r] = 0.f;

    // ---- prologue: V chunk 0 cp.async -> buf0, e chunk 0 LDG
    cpa16(sBbase + 0 * 2 * BBUF + bSt, vh);
    cpa16(sBbase + 0 * 2 * BBUF + bSt + 16, vh + 8);
    cpa16(sBbase + (0 * 2 + 1) * BBUF + bSt, vl);
    cpa16(sBbase + (0 * 2 + 1) * BBUF + bSt + 16, vl + 8);
    CP_COMMIT();
    float4 e0 = *(const float4*)&Sp[scol];
    float4 e1 = *(const float4*)&Sp[scol + 4];

    int buf = 0;
#pragma unroll 1
    for (int chunk = 0; chunk < SK / 32; chunk++) {
        // process e -> p: scale, write back, split, STS
        {
            float4 p0 = e0, p1 = e1;
            p0.x *= inv; p0.y *= inv; p0.z *= inv; p0.w *= inv;
            p1.x *= inv; p1.y *= inv; p1.z *= inv; p1.w *= inv;
            *(float4*)&Sp[chunk * 32 + scol] = p0;
            *(float4*)&Sp[chunk * 32 + scol + 4] = p1;
            HL h0 = split2(p0.x, p0.y), h1 = split2(p0.z, p0.w);
            HL h2 = split2(p1.x, p1.y), h3 = split2(p1.z, p1.w);
            uint4 hv = {h0.h, h1.h, h2.h, h3.h};
            uint4 lv = {h0.l, h1.l, h2.l, h3.l};
            *(uint4*)((char*)sA + (size_t)buf * 2 * ABUF + aSt) = hv;
            *(uint4*)((char*)sA + ((size_t)buf * 2 + 1) * ABUF + aSt) = lv;
        }
        CP_WAIT0();
        __syncthreads();

        // prefetch chunk+1 (safe: all warps past sync => prior MMA on buf^1 done)
        if (chunk < SK / 32 - 1) {
            int nb = buf ^ 1;
            size_t voff = (size_t)(chunk + 1) * 32 * DV;
            cpa16(sBbase + (uint32_t)nb * 2 * BBUF + bSt, vh + voff);
            cpa16(sBbase + (uint32_t)nb * 2 * BBUF + bSt + 16, vh + voff + 8);
            cpa16(sBbase + ((uint32_t)nb * 2 + 1) * BBUF + bSt, vl + voff);
            cpa16(sBbase + ((uint32_t)nb * 2 + 1) * BBUF + bSt + 16, vl + voff + 8);
            CP_COMMIT();
            e0 = *(const float4*)&Sp[(chunk + 1) * 32 + scol];
            e1 = *(const float4*)&Sp[(chunk + 1) * 32 + scol + 4];
        }

        // MMA on current buffer: 2 k16 steps
#pragma unroll
        for (int ks = 0; ks < 2; ks++) {
            const uint32_t k0 = ks * 16;
            uint32_t bh[4][2], bl[4][2];
#pragma unroll
            for (int jj = 0; jj < 2; jj++) {
                uint32_t badd = (uint32_t)buf * 2 * BBUF + k0 * BW * 2 + btoff + (uint32_t)(jj * 32);
                ldsm_x4_t(bh[2 * jj][0], bh[2 * jj][1], bh[2 * jj + 1][0], bh[2 * jj + 1][1],
                          sBbase + badd);
                ldsm_x4_t(bl[2 * jj][0], bl[2 * jj][1], bl[2 * jj + 1][0], bl[2 * jj + 1][1],
                          sBbase + badd + BBUF);
            }
#pragma unroll
            for (int i = 0; i < 2; i++) {
                uint32_t ar = (uint32_t)buf * 2 * ABUF +
                              (uint32_t)(((warpM * 32 + i * 16) * AW2 + k0) * 2) + aoff;
                uint32_t ah[4], al[4];
                ldsm_x4(ah[0], ah[1], ah[2], ah[3], sAbase + ar);
                ldsm_x4(al[0], al[1], al[2], al[3], sAbase + ar + ABUF);
#pragma unroll
                for (int j = 0; j < 4; j++) {
                    mma_bf16(c[i][j], ah, bh[j][0], bh[j][1]);
                    mma_bf16(c[i][j], ah, bl[j][0], bl[j][1]);
                    mma_bf16(c[i][j], al, bh[j][0], bh[j][1]);
                }
            }
        }
        buf ^= 1;
    }

    // epilogue
#pragma unroll
    for (int i = 0; i < 2; i++) {
        int r1 = q0 + warpM * 32 + i * 16 + gid;
#pragma unroll
        for (int j = 0; j < 4; j++) {
            int col = warpN * 32 + j * 8 + tig * 2;
            float2 v0 = {c[i][j][0], c[i][j][1]};
            float2 v1 = {c[i][j][2], c[i][j][3]};
            *(float2*)&out[((size_t)b * SQ + r1) * DV + col] = v0;
            *(float2*)&out[((size_t)b * SQ + r1 + 8) * DV + col] = v1;
        }
    }
}

// ---------------------------------------------------------------------------
extern "C" void kernel_launch(void* const* d_in, const int* in_sizes, int n_in,
                              void* d_out, int out_size) {
    const float* Q = (const float*)d_in[0];   // [B,SQ,DQ]
    const float* K = (const float*)d_in[1];   // [B,SK,DK]
    const float* V = (const float*)d_in[2];   // [B,SK,DV]
    const float* W = (const float*)d_in[3];   // [DQ,DK]

    float* out  = (float*)d_out;                          // [B,SQ,DV]
    float* wout = (float*)d_out + (size_t)NB * SQ * DV;   // [B,SQ,SK]

    zero_sum<<<NB * SQ / 256, 256>>>();
    prep_kv<<<NB * SK * DQK / 2048, 256>>>(K, V);
    qw_kernel<<<NB * SQ / 64, 256>>>(Q, W);

    dim3 sg(SK / 128, SQ / 128, NB);
    score_kernel<<<sg, 256>>>(wout);

    dim3 pg(SQ / 64, NB);
    pv_fused<<<pg, 256>>>(wout, out);
}

// round 7
// speedup vs baseline: 1.3065x; 1.3065x over previous
#include <cuda_runtime.h>
#include <cuda_bf16.h>
#include <cstdint>

#define NB 8
#define SQ 2048
#define SK 2048
#define DQK 128
#define DV 128

#define SW 24     // bf16 stride, k-major 16-col tiles (48B rows, odd 16B units)
#define AW 40     // bf16 stride for P tile rows, chunk 32 (80B = 5x16B odd)
#define BW 136    // bf16 stride for V tile rows (272B, 17x16B odd)

// Scratch: QW = Q @ W, [NB*SQ, DQK] fp32 = 8 MB
__device__ float g_qw[NB * SQ * DQK];

// ---------------------------------------------------------------------------
struct HL { uint32_t h, l; };

__device__ __forceinline__ HL split2(float x, float y) {
    __nv_bfloat162 hh = __floats2bfloat162_rn(x, y);
    float hx = __bfloat162float(__low2bfloat16(hh));
    float hy = __bfloat162float(__high2bfloat16(hh));
    __nv_bfloat162 ll = __floats2bfloat162_rn(x - hx, y - hy);
    HL r;
    r.h = *reinterpret_cast<uint32_t*>(&hh);
    r.l = *reinterpret_cast<uint32_t*>(&ll);
    return r;
}

__device__ __forceinline__ void mma_bf16(float* c, const uint32_t* a,
                                         uint32_t b0, uint32_t b1) {
    asm volatile(
        "mma.sync.aligned.m16n8k16.row.col.f32.bf16.bf16.f32 "
        "{%0,%1,%2,%3}, {%4,%5,%6,%7}, {%8,%9}, {%0,%1,%2,%3};"
        : "+f"(c[0]), "+f"(c[1]), "+f"(c[2]), "+f"(c[3])
        : "r"(a[0]), "r"(a[1]), "r"(a[2]), "r"(a[3]), "r"(b0), "r"(b1));
}

__device__ __forceinline__ void ldsm_x4(uint32_t& r0, uint32_t& r1, uint32_t& r2,
                                        uint32_t& r3, uint32_t addr) {
    asm volatile("ldmatrix.sync.aligned.m8n8.x4.shared.b16 {%0,%1,%2,%3}, [%4];"
                 : "=r"(r0), "=r"(r1), "=r"(r2), "=r"(r3) : "r"(addr));
}

__device__ __forceinline__ void ldsm_x4_t(uint32_t& r0, uint32_t& r1, uint32_t& r2,
                                          uint32_t& r3, uint32_t addr) {
    asm volatile("ldmatrix.sync.aligned.m8n8.x4.trans.shared.b16 {%0,%1,%2,%3}, [%4];"
                 : "=r"(r0), "=r"(r1), "=r"(r2), "=r"(r3) : "r"(addr));
}

// ---------------------------------------------------------------------------
// Kernel 1: QW = Q @ W  (fp32 FFMA; tiny fraction of runtime)
// ---------------------------------------------------------------------------
__global__ void qw_kernel(const float* __restrict__ Q, const float* __restrict__ W) {
    __shared__ float sAt[32][65];
    __shared__ float sB[32][128];

    const int tid = threadIdx.x;
    const int tx = tid & 15;
    const int ty = tid >> 4;
    const int m0 = blockIdx.x * 64;

    float acc[4][8];
#pragma unroll
    for (int i = 0; i < 4; i++)
#pragma unroll
        for (int j = 0; j < 8; j++) acc[i][j] = 0.f;

    for (int kk = 0; kk < DQK; kk += 32) {
#pragma unroll
        for (int r = 0; r < 8; r++) {
            int idx = tid + r * 256;
            int m = idx >> 5, k = idx & 31;
            sAt[k][m] = Q[(size_t)(m0 + m) * DQK + kk + k];
        }
#pragma unroll
        for (int r = 0; r < 16; r++) {
            int idx = tid + r * 256;
            int k = idx >> 7, n = idx & 127;
            sB[k][n] = W[(size_t)(kk + k) * DQK + n];
        }
        __syncthreads();

#pragma unroll
        for (int k = 0; k < 32; k++) {
            float a[4];
#pragma unroll
            for (int i = 0; i < 4; i++) a[i] = sAt[k][ty * 4 + i];
            float4 b0 = *(const float4*)&sB[k][tx * 8];
            float4 b1 = *(const float4*)&sB[k][tx * 8 + 4];
            float b[8] = {b0.x, b0.y, b0.z, b0.w, b1.x, b1.y, b1.z, b1.w};
#pragma unroll
            for (int i = 0; i < 4; i++)
#pragma unroll
                for (int j = 0; j < 8; j++) acc[i][j] = fmaf(a[i], b[j], acc[i][j]);
        }
        __syncthreads();
    }

#pragma unroll
    for (int i = 0; i < 4; i++) {
        size_t row = (size_t)(m0 + ty * 4 + i) * DQK + tx * 8;
        float4 v0 = {acc[i][0], acc[i][1], acc[i][2], acc[i][3]};
        float4 v1 = {acc[i][4], acc[i][5], acc[i][6], acc[i][7]};
        *(float4*)&g_qw[row] = v0;
        *(float4*)&g_qw[row + 4] = v1;
    }
}

// ---------------------------------------------------------------------------
// Kernel 2: S = QW @ K^T via bf16x3 mma.sync (R3 proven).
// grid (SK/128, SQ/128, NB), block 256 = 8 warps (2x4). Tile 128x128, k=16.
// ---------------------------------------------------------------------------
__global__ void __launch_bounds__(256, 2)
score_kernel(const float* __restrict__ Kmat, float* __restrict__ Wout) {
    __shared__ __align__(16) uint16_t sA[2][2][128 * SW];
    __shared__ __align__(16) uint16_t sB[2][2][128 * SW];

    const int tid = threadIdx.x;
    const int warp = tid >> 5, lane = tid & 31;
    const int warpM = warp >> 2, warpN = warp & 3;
    const int gid = lane >> 2, tig = lane & 3;

    const int s0 = blockIdx.x * 128;
    const int q0 = blockIdx.y * 128;
    const int b = blockIdx.z;

    const float* A = g_qw + ((size_t)b * SQ + q0) * DQK;
    const float* Bm = Kmat + ((size_t)b * SK + s0) * DQK;

    const int lrow = tid >> 1;
    const int lkb = (tid & 1) * 8;

    const int g = lane >> 3, lr = lane & 7;
    const uint32_t aoff = (uint32_t)(((((g & 1) * 8 + lr) * SW) + (g >> 1) * 8) * 2);
    const uint32_t boff = (uint32_t)((((warpN * 32 + (g >> 1) * 8 + lr) * SW) + (g & 1) * 8) * 2);

    const uint32_t sAbase = (uint32_t)__cvta_generic_to_shared(&sA[0][0][0]);
    const uint32_t sBbase = (uint32_t)__cvta_generic_to_shared(&sB[0][0][0]);
    const uint32_t HLSTRIDE = 128 * SW * 2;

    float c[4][4][4];
#pragma unroll
    for (int i = 0; i < 4; i++)
#pragma unroll
        for (int j = 0; j < 4; j++)
#pragma unroll
            for (int r = 0; r < 4; r++) c[i][j][r] = 0.f;

    float4 pa0 = *(const float4*)&A[(size_t)lrow * DQK + lkb];
    float4 pa1 = *(const float4*)&A[(size_t)lrow * DQK + lkb + 4];
    float4 pb0 = *(const float4*)&Bm[(size_t)lrow * DQK + lkb];
    float4 pb1 = *(const float4*)&Bm[(size_t)lrow * DQK + lkb + 4];
    {
        HL q0h = split2(pa0.x, pa0.y), q1h = split2(pa0.z, pa0.w);
        HL q2h = split2(pa1.x, pa1.y), q3h = split2(pa1.z, pa1.w);
        uint4 hv = {q0h.h, q1h.h, q2h.h, q3h.h};
        uint4 lv = {q0h.l, q1h.l, q2h.l, q3h.l};
        *(uint4*)&sA[0][0][lrow * SW + lkb] = hv;
        *(uint4*)&sA[0][1][lrow * SW + lkb] = lv;
        HL r0h = split2(pb0.x, pb0.y), r1h = split2(pb0.z, pb0.w);
        HL r2h = split2(pb1.x, pb1.y), r3h = split2(pb1.z, pb1.w);
        uint4 hw = {r0h.h, r1h.h, r2h.h, r3h.h};
        uint4 lw = {r0h.l, r1h.l, r2h.l, r3h.l};
        *(uint4*)&sB[0][0][lrow * SW + lkb] = hw;
        *(uint4*)&sB[0][1][lrow * SW + lkb] = lw;
    }
    __syncthreads();

    int buf = 0;
#pragma unroll 1
    for (int chunk = 0; chunk < 8; chunk++) {
        if (chunk < 7) {
            int kk = (chunk + 1) * 16;
            pa0 = *(const float4*)&A[(size_t)lrow * DQK + kk + lkb];
            pa1 = *(const float4*)&A[(size_t)lrow * DQK + kk + lkb + 4];
            pb0 = *(const float4*)&Bm[(size_t)lrow * DQK + kk + lkb];
            pb1 = *(const float4*)&Bm[(size_t)lrow * DQK + kk + lkb + 4];
        }

        {
            const uint32_t bhi = sBbase + (uint32_t)buf * 2 * HLSTRIDE + boff;
            const uint32_t blo = bhi + HLSTRIDE;
            uint32_t bh[4][2], bl[4][2];
#pragma unroll
            for (int jj = 0; jj < 2; jj++) {
                ldsm_x4(bh[2 * jj][0], bh[2 * jj][1], bh[2 * jj + 1][0], bh[2 * jj + 1][1],
                        bhi + (uint32_t)(jj * 16 * SW * 2));
                ldsm_x4(bl[2 * jj][0], bl[2 * jj][1], bl[2 * jj + 1][0], bl[2 * jj + 1][1],
                        blo + (uint32_t)(jj * 16 * SW * 2));
            }
            const uint32_t ahi = sAbase + (uint32_t)buf * 2 * HLSTRIDE + aoff;
            const uint32_t alo = ahi + HLSTRIDE;
#pragma unroll
            for (int i = 0; i < 4; i++) {
                uint32_t arow = (uint32_t)((warpM * 64 + i * 16) * SW * 2);
                uint32_t ah[4], al[4];
                ldsm_x4(ah[0], ah[1], ah[2], ah[3], ahi + arow);
                ldsm_x4(al[0], al[1], al[2], al[3], alo + arow);
#pragma unroll
                for (int j = 0; j < 4; j++) {
                    mma_bf16(c[i][j], ah, bh[j][0], bh[j][1]);
                    mma_bf16(c[i][j], ah, bl[j][0], bl[j][1]);
                    mma_bf16(c[i][j], al, bh[j][0], bh[j][1]);
                }
            }
        }

        if (chunk < 7) {
            int nb = buf ^ 1;
            HL q0h = split2(pa0.x, pa0.y), q1h = split2(pa0.z, pa0.w);
            HL q2h = split2(pa1.x, pa1.y), q3h = split2(pa1.z, pa1.w);
            uint4 hv = {q0h.h, q1h.h, q2h.h, q3h.h};
            uint4 lv = {q0h.l, q1h.l, q2h.l, q3h.l};
            *(uint4*)&sA[nb][0][lrow * SW + lkb] = hv;
            *(uint4*)&sA[nb][1][lrow * SW + lkb] = lv;
            HL r0h = split2(pb0.x, pb0.y), r1h = split2(pb0.z, pb0.w);
            HL r2h = split2(pb1.x, pb1.y), r3h = split2(pb1.z, pb1.w);
            uint4 hw = {r0h.h, r1h.h, r2h.h, r3h.h};
            uint4 lw = {r0h.l, r1h.l, r2h.l, r3h.l};
            *(uint4*)&sB[nb][0][lrow * SW + lkb] = hw;
            *(uint4*)&sB[nb][1][lrow * SW + lkb] = lw;
            __syncthreads();
        }
        buf ^= 1;
    }

#pragma unroll
    for (int i = 0; i < 4; i++) {
        int r1 = q0 + warpM * 64 + i * 16 + gid;
#pragma unroll
        for (int j = 0; j < 4; j++) {
            int col = s0 + warpN * 32 + j * 8 + tig * 2;
            float2 v0 = {c[i][j][0], c[i][j][1]};
            float2 v1 = {c[i][j][2], c[i][j][3]};
            *(float2*)&Wout[((size_t)b * SQ + r1) * SK + col] = v0;
            *(float2*)&Wout[((size_t)b * SQ + r1 + 8) * SK + col] = v1;
        }
    }
}

// ---------------------------------------------------------------------------
// Kernel 3: in-place row softmax over SK=2048, float4-vectorized (R3 proven).
// ---------------------------------------------------------------------------
__global__ void softmax_kernel(float* __restrict__ w) {
    float4* p = (float4*)(w + (size_t)blockIdx.x * SK);
    const int t = threadIdx.x;
    __shared__ float red[8];

    float4 v0 = p[t];
    float4 v1 = p[t + 256];
    float mx = fmaxf(fmaxf(fmaxf(v0.x, v0.y), fmaxf(v0.z, v0.w)),
                     fmaxf(fmaxf(v1.x, v1.y), fmaxf(v1.z, v1.w)));
#pragma unroll
    for (int o = 16; o > 0; o >>= 1) mx = fmaxf(mx, __shfl_xor_sync(~0u, mx, o));
    if ((t & 31) == 0) red[t >> 5] = mx;
    __syncthreads();
    float bm = red[0];
#pragma unroll
    for (int i = 1; i < 8; i++) bm = fmaxf(bm, red[i]);
    __syncthreads();

    v0.x = __expf(v0.x - bm); v0.y = __expf(v0.y - bm);
    v0.z = __expf(v0.z - bm); v0.w = __expf(v0.w - bm);
    v1.x = __expf(v1.x - bm); v1.y = __expf(v1.y - bm);
    v1.z = __expf(v1.z - bm); v1.w = __expf(v1.w - bm);
    float sum = v0.x + v0.y + v0.z + v0.w + v1.x + v1.y + v1.z + v1.w;
#pragma unroll
    for (int o = 16; o > 0; o >>= 1) sum += __shfl_xor_sync(~0u, sum, o);
    if ((t & 31) == 0) red[t >> 5] = sum;
    __syncthreads();
    float tot = 0.f;
#pragma unroll
    for (int i = 0; i < 8; i++) tot += red[i];
    float inv = 1.f / tot;
    v0.x *= inv; v0.y *= inv; v0.z *= inv; v0.w *= inv;
    v1.x *= inv; v1.y *= inv; v1.z *= inv; v1.w *= inv;
    p[t] = v0;
    p[t + 256] = v1;
}

// ---------------------------------------------------------------------------
// Kernel 4: out = P @ V via bf16x3 mma.sync. R3 structure, s-chunk 32:
// doubled prefetch window (covers P DRAM latency), half the syncs.
// grid (SQ/64, NB) = 256 CTAs, block 256 = 8 warps (2 Mwarps x 4 Nwarps).
// ---------------------------------------------------------------------------
__global__ void __launch_bounds__(256, 2)
pv_kernel(const float* __restrict__ P, const float* __restrict__ V,
          float* __restrict__ out) {
    __shared__ __align__(16) uint16_t sA[2][2][64 * AW];   // P tile [q64][s32]
    __shared__ __align__(16) uint16_t sB[2][2][32 * BW];   // V tile [s32][v128]

    const int tid = threadIdx.x;
    const int warp = tid >> 5, lane = tid & 31;
    const int warpM = warp >> 2, warpN = warp & 3;
    const int gid = lane >> 2, tig = lane & 3;

    const int q0 = blockIdx.x * 64;
    const int b = blockIdx.y;

    const float* Pb = P + ((size_t)b * SQ + q0) * SK;
    const float* Vb = V + (size_t)b * SK * DV;

    // loader indices
    const int arow = tid >> 2;            // 0..63
    const int akb = (tid & 3) * 8;        // 0,8,16,24
    const int bs = tid >> 3;              // 0..31
    const int bv = (tid & 7) * 16;        // 0..112

    // ldmatrix per-lane offsets
    const int g = lane >> 3, lr = lane & 7;
    const uint32_t aoff = (uint32_t)(((((g & 1) * 8 + lr) * AW) + (g >> 1) * 8) * 2);
    const uint32_t btoff = (uint32_t)((((g & 1) * 8 + lr) * BW + (warpN * 32 + (g >> 1) * 8)) * 2);

    const uint32_t sAbase = (uint32_t)__cvta_generic_to_shared(&sA[0][0][0]);
    const uint32_t sBbase = (uint32_t)__cvta_generic_to_shared(&sB[0][0][0]);
    const uint32_t AHL = 64 * AW * 2;
    const uint32_t BHL = 32 * BW * 2;

    float c[2][4][4];
#pragma unroll
    for (int i = 0; i < 2; i++)
#pragma unroll
        for (int j = 0; j < 4; j++)
#pragma unroll
            for (int r = 0; r < 4; r++) c[i][j][r] = 0.f;

    // ---- prologue: chunk 0 -> buf 0
    float4 pa0 = *(const float4*)&Pb[(size_t)arow * SK + akb];
    float4 pa1 = *(const float4*)&Pb[(size_t)arow * SK + akb + 4];
    float4 pv0 = *(const float4*)&Vb[(size_t)bs * DV + bv];
    float4 pv1 = *(const float4*)&Vb[(size_t)bs * DV + bv + 4];
    float4 pv2 = *(const float4*)&Vb[(size_t)bs * DV + bv + 8];
    float4 pv3 = *(const float4*)&Vb[(size_t)bs * DV + bv + 12];
    {
        HL a0 = split2(pa0.x, pa0.y), a1 = split2(pa0.z, pa0.w);
        HL a2 = split2(pa1.x, pa1.y), a3 = split2(pa1.z, pa1.w);
        uint4 hv = {a0.h, a1.h, a2.h, a3.h};
        uint4 lv = {a0.l, a1.l, a2.l, a3.l};
        *(uint4*)&sA[0][0][arow * AW + akb] = hv;
        *(uint4*)&sA[0][1][arow * AW + akb] = lv;
        HL w0 = split2(pv0.x, pv0.y), w1 = split2(pv0.z, pv0.w);
        HL w2 = split2(pv1.x, pv1.y), w3 = split2(pv1.z, pv1.w);
        HL w4 = split2(pv2.x, pv2.y), w5 = split2(pv2.z, pv2.w);
        HL w6 = split2(pv3.x, pv3.y), w7 = split2(pv3.z, pv3.w);
        uint4 hw0 = {w0.h, w1.h, w2.h, w3.h};
        uint4 hw1 = {w4.h, w5.h, w6.h, w7.h};
        uint4 lw0 = {w0.l, w1.l, w2.l, w3.l};
        uint4 lw1 = {w4.l, w5.l, w6.l, w7.l};
        *(uint4*)&sB[0][0][bs * BW + bv] = hw0;
        *(uint4*)&sB[0][0][bs * BW + bv + 8] = hw1;
        *(uint4*)&sB[0][1][bs * BW + bv] = lw0;
        *(uint4*)&sB[0][1][bs * BW + bv + 8] = lw1;
    }
    __syncthreads();

    int buf = 0;
#pragma unroll 1
    for (int chunk = 0; chunk < SK / 32; chunk++) {
        // prefetch chunk+1 from gmem (issued before the MMA block)
        if (chunk < SK / 32 - 1) {
            int ss = (chunk + 1) * 32;
            pa0 = *(const float4*)&Pb[(size_t)arow * SK + ss + akb];
            pa1 = *(const float4*)&Pb[(size_t)arow * SK + ss + akb + 4];
            pv0 = *(const float4*)&Vb[(size_t)(ss + bs) * DV + bv];
            pv1 = *(const float4*)&Vb[(size_t)(ss + bs) * DV + bv + 4];
            pv2 = *(const float4*)&Vb[(size_t)(ss + bs) * DV + bv + 8];
            pv3 = *(const float4*)&Vb[(size_t)(ss + bs) * DV + bv + 12];
        }

        // MMA on current buffer: 2 k16 steps
#pragma unroll
        for (int ks = 0; ks < 2; ks++) {
            const uint32_t k0 = ks * 16;
            uint32_t bh[4][2], bl[4][2];
#pragma unroll
            for (int jj = 0; jj < 2; jj++) {
                uint32_t badd = (uint32_t)buf * 2 * BHL + k0 * BW * 2 + btoff + (uint32_t)(jj * 32);
                ldsm_x4_t(bh[2 * jj][0], bh[2 * jj][1], bh[2 * jj + 1][0], bh[2 * jj + 1][1],
                          sBbase + badd);
                ldsm_x4_t(bl[2 * jj][0], bl[2 * jj][1], bl[2 * jj + 1][0], bl[2 * jj + 1][1],
                          sBbase + badd + BHL);
            }
#pragma unroll
            for (int i = 0; i < 2; i++) {
                uint32_t ar = (uint32_t)buf * 2 * AHL +
                              (uint32_t)(((warpM * 32 + i * 16) * AW + k0) * 2) + aoff;
                uint32_t ah[4], al[4];
                ldsm_x4(ah[0], ah[1], ah[2], ah[3], sAbase + ar);
                ldsm_x4(al[0], al[1], al[2], al[3], sAbase + ar + AHL);
#pragma unroll
                for (int j = 0; j < 4; j++) {
                    mma_bf16(c[i][j], ah, bh[j][0], bh[j][1]);
                    mma_bf16(c[i][j], ah, bl[j][0], bl[j][1]);
                    mma_bf16(c[i][j], al, bh[j][0], bh[j][1]);
                }
            }
        }

        // stage chunk+1 into other buffer
        if (chunk < SK / 32 - 1) {
            int nb = buf ^ 1;
            HL a0 = split2(pa0.x, pa0.y), a1 = split2(pa0.z, pa0.w);
            HL a2 = split2(pa1.x, pa1.y), a3 = split2(pa1.z, pa1.w);
            uint4 hv = {a0.h, a1.h, a2.h, a3.h};
            uint4 lv = {a0.l, a1.l, a2.l, a3.l};
            *(uint4*)&sA[nb][0][arow * AW + akb] = hv;
            *(uint4*)&sA[nb][1][arow * AW + akb] = lv;
            HL w0 = split2(pv0.x, pv0.y), w1 = split2(pv0.z, pv0.w);
            HL w2 = split2(pv1.x, pv1.y), w3 = split2(pv1.z, pv1.w);
            HL w4 = split2(pv2.x, pv2.y), w5 = split2(pv2.z, pv2.w);
            HL w6 = split2(pv3.x, pv3.y), w7 = split2(pv3.z, pv3.w);
            uint4 hw0 = {w0.h, w1.h, w2.h, w3.h};
            uint4 hw1 = {w4.h, w5.h, w6.h, w7.h};
            uint4 lw0 = {w0.l, w1.l, w2.l, w3.l};
            uint4 lw1 = {w4.l, w5.l, w6.l, w7.l};
            *(uint4*)&sB[nb][0][bs * BW + bv] = hw0;
            *(uint4*)&sB[nb][0][bs * BW + bv + 8] = hw1;
            *(uint4*)&sB[nb][1][bs * BW + bv] = lw0;
            *(uint4*)&sB[nb][1][bs * BW + bv + 8] = lw1;
            __syncthreads();
        }
        buf ^= 1;
    }

    // epilogue
#pragma unroll
    for (int i = 0; i < 2; i++) {
        int r1 = q0 + warpM * 32 + i * 16 + gid;
#pragma unroll
        for (int j = 0; j < 4; j++) {
            int col = warpN * 32 + j * 8 + tig * 2;
            float2 v0 = {c[i][j][0], c[i][j][1]};
            float2 v1 = {c[i][j][2], c[i][j][3]};
            *(float2*)&out[((size_t)b * SQ + r1) * DV + col] = v0;
            *(float2*)&out[((size_t)b * SQ + r1 + 8) * DV + col] = v1;
        }
    }
}

// ---------------------------------------------------------------------------
extern "C" void kernel_launch(void* const* d_in, const int* in_sizes, int n_in,
                              void* d_out, int out_size) {
    const float* Q = (const float*)d_in[0];   // [B,SQ,DQ]
    const float* K = (const float*)d_in[1];   // [B,SK,DK]
    const float* V = (const float*)d_in[2];   // [B,SK,DV]
    const float* W = (const float*)d_in[3];   // [DQ,DK]

    float* out  = (float*)d_out;                          // [B,SQ,DV]
    float* wout = (float*)d_out + (size_t)NB * SQ * DV;   // [B,SQ,SK]

    qw_kernel<<<NB * SQ / 64, 256>>>(Q, W);

    dim3 sg(SK / 128, SQ / 128, NB);
    score_kernel<<<sg, 256>>>(K, wout);

    softmax_kernel<<<NB * SQ, 256>>>(wout);

    dim3 pg(SQ / 64, NB);
    pv_kernel<<<pg, 256>>>(wout, V, out);
}

// round 8
// speedup vs baseline: 1.5799x; 1.2093x over previous
#include <cuda_runtime.h>
#include <cuda_bf16.h>
#include <cuda_fp16.h>
#include <cstdint>

#define NB 8
#define SQ 2048
#define SK 2048
#define DQK 128
#define DV 128

#define SW 24     // bf16 stride, k-major 16-col tiles (48B rows, odd 16B units)
#define AW 40     // fp16 stride for P tile rows, chunk 32 (80B = 5x16B odd)
#define BW 136    // fp16 stride for V tile rows (272B, 17x16B odd)

// Scratch
__device__ float    g_qw[NB * SQ * DQK];        // QW fp32
__device__ __half   g_pf16[(size_t)NB * SQ * SK]; // P (normalized weights) fp16
__device__ __half   g_vf16[NB * SK * DV];       // V fp16

// ---------------------------------------------------------------------------
struct HL { uint32_t h, l; };

__device__ __forceinline__ HL split2(float x, float y) {
    __nv_bfloat162 hh = __floats2bfloat162_rn(x, y);
    float hx = __bfloat162float(__low2bfloat16(hh));
    float hy = __bfloat162float(__high2bfloat16(hh));
    __nv_bfloat162 ll = __floats2bfloat162_rn(x - hx, y - hy);
    HL r;
    r.h = *reinterpret_cast<uint32_t*>(&hh);
    r.l = *reinterpret_cast<uint32_t*>(&ll);
    return r;
}

__device__ __forceinline__ void mma_bf16(float* c, const uint32_t* a,
                                         uint32_t b0, uint32_t b1) {
    asm volatile(
        "mma.sync.aligned.m16n8k16.row.col.f32.bf16.bf16.f32 "
        "{%0,%1,%2,%3}, {%4,%5,%6,%7}, {%8,%9}, {%0,%1,%2,%3};"
        : "+f"(c[0]), "+f"(c[1]), "+f"(c[2]), "+f"(c[3])
        : "r"(a[0]), "r"(a[1]), "r"(a[2]), "r"(a[3]), "r"(b0), "r"(b1));
}

__device__ __forceinline__ void mma_f16(float* c, const uint32_t* a,
                                        uint32_t b0, uint32_t b1) {
    asm volatile(
        "mma.sync.aligned.m16n8k16.row.col.f32.f16.f16.f32 "
        "{%0,%1,%2,%3}, {%4,%5,%6,%7}, {%8,%9}, {%0,%1,%2,%3};"
        : "+f"(c[0]), "+f"(c[1]), "+f"(c[2]), "+f"(c[3])
        : "r"(a[0]), "r"(a[1]), "r"(a[2]), "r"(a[3]), "r"(b0), "r"(b1));
}

__device__ __forceinline__ void ldsm_x4(uint32_t& r0, uint32_t& r1, uint32_t& r2,
                                        uint32_t& r3, uint32_t addr) {
    asm volatile("ldmatrix.sync.aligned.m8n8.x4.shared.b16 {%0,%1,%2,%3}, [%4];"
                 : "=r"(r0), "=r"(r1), "=r"(r2), "=r"(r3) : "r"(addr));
}

__device__ __forceinline__ void ldsm_x4_t(uint32_t& r0, uint32_t& r1, uint32_t& r2,
                                          uint32_t& r3, uint32_t addr) {
    asm volatile("ldmatrix.sync.aligned.m8n8.x4.trans.shared.b16 {%0,%1,%2,%3}, [%4];"
                 : "=r"(r0), "=r"(r1), "=r"(r2), "=r"(r3) : "r"(addr));
}

__device__ __forceinline__ void cpa16(uint32_t dst, const void* src) {
    asm volatile("cp.async.ca.shared.global [%0], [%1], 16;" :: "r"(dst), "l"(src));
}
#define CP_COMMIT() asm volatile("cp.async.commit_group;")
#define CP_WAIT0()  asm volatile("cp.async.wait_group 0;")
#define CP_WAIT1()  asm volatile("cp.async.wait_group 1;")

// ---------------------------------------------------------------------------
// Prep: V fp32 -> fp16.
// ---------------------------------------------------------------------------
__global__ void prep_v(const float* __restrict__ V) {
    size_t i = ((size_t)blockIdx.x * 256 + threadIdx.x) * 8;
    float4 a0 = *(const float4*)&V[i];
    float4 a1 = *(const float4*)&V[i + 4];
    __half2 h0 = __floats2half2_rn(a0.x, a0.y);
    __half2 h1 = __floats2half2_rn(a0.z, a0.w);
    __half2 h2 = __floats2half2_rn(a1.x, a1.y);
    __half2 h3 = __floats2half2_rn(a1.z, a1.w);
    uint4 v = {*(uint32_t*)&h0, *(uint32_t*)&h1, *(uint32_t*)&h2, *(uint32_t*)&h3};
    *(uint4*)&g_vf16[i] = v;
}

// ---------------------------------------------------------------------------
// Kernel 1: QW = Q @ W  (fp32 FFMA; tiny fraction of runtime)
// ---------------------------------------------------------------------------
__global__ void qw_kernel(const float* __restrict__ Q, const float* __restrict__ W) {
    __shared__ float sAt[32][65];
    __shared__ float sB[32][128];

    const int tid = threadIdx.x;
    const int tx = tid & 15;
    const int ty = tid >> 4;
    const int m0 = blockIdx.x * 64;

    float acc[4][8];
#pragma unroll
    for (int i = 0; i < 4; i++)
#pragma unroll
        for (int j = 0; j < 8; j++) acc[i][j] = 0.f;

    for (int kk = 0; kk < DQK; kk += 32) {
#pragma unroll
        for (int r = 0; r < 8; r++) {
            int idx = tid + r * 256;
            int m = idx >> 5, k = idx & 31;
            sAt[k][m] = Q[(size_t)(m0 + m) * DQK + kk + k];
        }
#pragma unroll
        for (int r = 0; r < 16; r++) {
            int idx = tid + r * 256;
            int k = idx >> 7, n = idx & 127;
            sB[k][n] = W[(size_t)(kk + k) * DQK + n];
        }
        __syncthreads();

#pragma unroll
        for (int k = 0; k < 32; k++) {
            float a[4];
#pragma unroll
            for (int i = 0; i < 4; i++) a[i] = sAt[k][ty * 4 + i];
            float4 b0 = *(const float4*)&sB[k][tx * 8];
            float4 b1 = *(const float4*)&sB[k][tx * 8 + 4];
            float b[8] = {b0.x, b0.y, b0.z, b0.w, b1.x, b1.y, b1.z, b1.w};
#pragma unroll
            for (int i = 0; i < 4; i++)
#pragma unroll
                for (int j = 0; j < 8; j++) acc[i][j] = fmaf(a[i], b[j], acc[i][j]);
        }
        __syncthreads();
    }

#pragma unroll
    for (int i = 0; i < 4; i++) {
        size_t row = (size_t)(m0 + ty * 4 + i) * DQK + tx * 8;
        float4 v0 = {acc[i][0], acc[i][1], acc[i][2], acc[i][3]};
        float4 v1 = {acc[i][4], acc[i][5], acc[i][6], acc[i][7]};
        *(float4*)&g_qw[row] = v0;
        *(float4*)&g_qw[row + 4] = v1;
    }
}

// ---------------------------------------------------------------------------
// Kernel 2: S = QW @ K^T via bf16x3 mma.sync (R3 proven, unchanged).
// ---------------------------------------------------------------------------
__global__ void __launch_bounds__(256, 2)
score_kernel(const float* __restrict__ Kmat, float* __restrict__ Wout) {
    __shared__ __align__(16) uint16_t sA[2][2][128 * SW];
    __shared__ __align__(16) uint16_t sB[2][2][128 * SW];

    const int tid = threadIdx.x;
    const int warp = tid >> 5, lane = tid & 31;
    const int warpM = warp >> 2, warpN = warp & 3;
    const int gid = lane >> 2, tig = lane & 3;

    const int s0 = blockIdx.x * 128;
    const int q0 = blockIdx.y * 128;
    const int b = blockIdx.z;

    const float* A = g_qw + ((size_t)b * SQ + q0) * DQK;
    const float* Bm = Kmat + ((size_t)b * SK + s0) * DQK;

    const int lrow = tid >> 1;
    const int lkb = (tid & 1) * 8;

    const int g = lane >> 3, lr = lane & 7;
    const uint32_t aoff = (uint32_t)(((((g & 1) * 8 + lr) * SW) + (g >> 1) * 8) * 2);
    const uint32_t boff = (uint32_t)((((warpN * 32 + (g >> 1) * 8 + lr) * SW) + (g & 1) * 8) * 2);

    const uint32_t sAbase = (uint32_t)__cvta_generic_to_shared(&sA[0][0][0]);
    const uint32_t sBbase = (uint32_t)__cvta_generic_to_shared(&sB[0][0][0]);
    const uint32_t HLSTRIDE = 128 * SW * 2;

    float c[4][4][4];
#pragma unroll
    for (int i = 0; i < 4; i++)
#pragma unroll
        for (int j = 0; j < 4; j++)
#pragma unroll
            for (int r = 0; r < 4; r++) c[i][j][r] = 0.f;

    float4 pa0 = *(const float4*)&A[(size_t)lrow * DQK + lkb];
    float4 pa1 = *(const float4*)&A[(size_t)lrow * DQK + lkb + 4];
    float4 pb0 = *(const float4*)&Bm[(size_t)lrow * DQK + lkb];
    float4 pb1 = *(const float4*)&Bm[(size_t)lrow * DQK + lkb + 4];
    {
        HL q0h = split2(pa0.x, pa0.y), q1h = split2(pa0.z, pa0.w);
        HL q2h = split2(pa1.x, pa1.y), q3h = split2(pa1.z, pa1.w);
        uint4 hv = {q0h.h, q1h.h, q2h.h, q3h.h};
        uint4 lv = {q0h.l, q1h.l, q2h.l, q3h.l};
        *(uint4*)&sA[0][0][lrow * SW + lkb] = hv;
        *(uint4*)&sA[0][1][lrow * SW + lkb] = lv;
        HL r0h = split2(pb0.x, pb0.y), r1h = split2(pb0.z, pb0.w);
        HL r2h = split2(pb1.x, pb1.y), r3h = split2(pb1.z, pb1.w);
        uint4 hw = {r0h.h, r1h.h, r2h.h, r3h.h};
        uint4 lw = {r0h.l, r1h.l, r2h.l, r3h.l};
        *(uint4*)&sB[0][0][lrow * SW + lkb] = hw;
        *(uint4*)&sB[0][1][lrow * SW + lkb] = lw;
    }
    __syncthreads();

    int buf = 0;
#pragma unroll 1
    for (int chunk = 0; chunk < 8; chunk++) {
        if (chunk < 7) {
            int kk = (chunk + 1) * 16;
            pa0 = *(const float4*)&A[(size_t)lrow * DQK + kk + lkb];
            pa1 = *(const float4*)&A[(size_t)lrow * DQK + kk + lkb + 4];
            pb0 = *(const float4*)&Bm[(size_t)lrow * DQK + kk + lkb];
            pb1 = *(const float4*)&Bm[(size_t)lrow * DQK + kk + lkb + 4];
        }

        {
            const uint32_t bhi = sBbase + (uint32_t)buf * 2 * HLSTRIDE + boff;
            const uint32_t blo = bhi + HLSTRIDE;
            uint32_t bh[4][2], bl[4][2];
#pragma unroll
            for (int jj = 0; jj < 2; jj++) {
                ldsm_x4(bh[2 * jj][0], bh[2 * jj][1], bh[2 * jj + 1][0], bh[2 * jj + 1][1],
                        bhi + (uint32_t)(jj * 16 * SW * 2));
                ldsm_x4(bl[2 * jj][0], bl[2 * jj][1], bl[2 * jj + 1][0], bl[2 * jj + 1][1],
                        blo + (uint32_t)(jj * 16 * SW * 2));
            }
            const uint32_t ahi = sAbase + (uint32_t)buf * 2 * HLSTRIDE + aoff;
            const uint32_t alo = ahi + HLSTRIDE;
#pragma unroll
            for (int i = 0; i < 4; i++) {
                uint32_t arow = (uint32_t)((warpM * 64 + i * 16) * SW * 2);
                uint32_t ah[4], al[4];
                ldsm_x4(ah[0], ah[1], ah[2], ah[3], ahi + arow);
                ldsm_x4(al[0], al[1], al[2], al[3], alo + arow);
#pragma unroll
                for (int j = 0; j < 4; j++) {
                    mma_bf16(c[i][j], ah, bh[j][0], bh[j][1]);
                    mma_bf16(c[i][j], ah, bl[j][0], bl[j][1]);
                    mma_bf16(c[i][j], al, bh[j][0], bh[j][1]);
                }
            }
        }

        if (chunk < 7) {
            int nb = buf ^ 1;
            HL q0h = split2(pa0.x, pa0.y), q1h = split2(pa0.z, pa0.w);
            HL q2h = split2(pa1.x, pa1.y), q3h = split2(pa1.z, pa1.w);
            uint4 hv = {q0h.h, q1h.h, q2h.h, q3h.h};
            uint4 lv = {q0h.l, q1h.l, q2h.l, q3h.l};
            *(uint4*)&sA[nb][0][lrow * SW + lkb] = hv;
            *(uint4*)&sA[nb][1][lrow * SW + lkb] = lv;
            HL r0h = split2(pb0.x, pb0.y), r1h = split2(pb0.z, pb0.w);
            HL r2h = split2(pb1.x, pb1.y), r3h = split2(pb1.z, pb1.w);
            uint4 hw = {r0h.h, r1h.h, r2h.h, r3h.h};
            uint4 lw = {r0h.l, r1h.l, r2h.l, r3h.l};
            *(uint4*)&sB[nb][0][lrow * SW + lkb] = hw;
            *(uint4*)&sB[nb][1][lrow * SW + lkb] = lw;
            __syncthreads();
        }
        buf ^= 1;
    }

#pragma unroll
    for (int i = 0; i < 4; i++) {
        int r1 = q0 + warpM * 64 + i * 16 + gid;
#pragma unroll
        for (int j = 0; j < 4; j++) {
            int col = s0 + warpN * 32 + j * 8 + tig * 2;
            float2 v0 = {c[i][j][0], c[i][j][1]};
            float2 v1 = {c[i][j][2], c[i][j][3]};
            *(float2*)&Wout[((size_t)b * SQ + r1) * SK + col] = v0;
            *(float2*)&Wout[((size_t)b * SQ + r1 + 8) * SK + col] = v1;
        }
    }
}

// ---------------------------------------------------------------------------
// Kernel 3: in-place row softmax, also emits fp16 copy of P for pv.
// ---------------------------------------------------------------------------
__global__ void softmax_kernel(float* __restrict__ w) {
    const size_t rowoff = (size_t)blockIdx.x * SK;
    float4* p = (float4*)(w + rowoff);
    const int t = threadIdx.x;
    __shared__ float red[8];

    float4 v0 = p[t];
    float4 v1 = p[t + 256];
    float mx = fmaxf(fmaxf(fmaxf(v0.x, v0.y), fmaxf(v0.z, v0.w)),
                     fmaxf(fmaxf(v1.x, v1.y), fmaxf(v1.z, v1.w)));
#pragma unroll
    for (int o = 16; o > 0; o >>= 1) mx = fmaxf(mx, __shfl_xor_sync(~0u, mx, o));
    if ((t & 31) == 0) red[t >> 5] = mx;
    __syncthreads();
    float bm = red[0];
#pragma unroll
    for (int i = 1; i < 8; i++) bm = fmaxf(bm, red[i]);
    __syncthreads();

    v0.x = __expf(v0.x - bm); v0.y = __expf(v0.y - bm);
    v0.z = __expf(v0.z - bm); v0.w = __expf(v0.w - bm);
    v1.x = __expf(v1.x - bm); v1.y = __expf(v1.y - bm);
    v1.z = __expf(v1.z - bm); v1.w = __expf(v1.w - bm);
    float sum = v0.x + v0.y + v0.z + v0.w + v1.x + v1.y + v1.z + v1.w;
#pragma unroll
    for (int o = 16; o > 0; o >>= 1) sum += __shfl_xor_sync(~0u, sum, o);
    if ((t & 31) == 0) red[t >> 5] = sum;
    __syncthreads();
    float tot = 0.f;
#pragma unroll
    for (int i = 0; i < 8; i++) tot += red[i];
    float inv = 1.f / tot;
    v0.x *= inv; v0.y *= inv; v0.z *= inv; v0.w *= inv;
    v1.x *= inv; v1.y *= inv; v1.z *= inv; v1.w *= inv;
    p[t] = v0;
    p[t + 256] = v1;

    // fp16 copy for pv
    __half2 h0 = __floats2half2_rn(v0.x, v0.y);
    __half2 h1 = __floats2half2_rn(v0.z, v0.w);
    __half2 h2 = __floats2half2_rn(v1.x, v1.y);
    __half2 h3 = __floats2half2_rn(v1.z, v1.w);
    uint2 a = {*(uint32_t*)&h0, *(uint32_t*)&h1};
    uint2 bb = {*(uint32_t*)&h2, *(uint32_t*)&h3};
    *(uint2*)&g_pf16[rowoff + t * 4] = a;
    *(uint2*)&g_pf16[rowoff + 1024 + t * 4] = bb;
}

// ---------------------------------------------------------------------------
// Kernel 4: out = P @ V, single-pass fp16 mma. Operands streamed gmem->smem
// via cp.async (no register staging). grid (SQ/64, NB), 256 thr (2x4 warps),
// s-chunk 32, double buffered, copy of c+1 overlaps MMA of c.
// ---------------------------------------------------------------------------
__global__ void __launch_bounds__(256, 3)
pv_kernel(float* __restrict__ out) {
    __shared__ __align__(16) __half sA[2][64 * AW];   // P tile [q64][s32]
    __shared__ __align__(16) __half sB[2][32 * BW];   // V tile [s32][v128]

    const int tid = threadIdx.x;
    const int warp = tid >> 5, lane = tid & 31;
    const int warpM = warp >> 2, warpN = warp & 3;
    const int gid = lane >> 2, tig = lane & 3;

    const int q0 = blockIdx.x * 64;
    const int b = blockIdx.y;

    // cp.async source pointers
    const int prow = tid >> 2;              // 0..63
    const int pseg = (tid & 3) * 8;         // 0,8,16,24
    const __half* Psrc = g_pf16 + ((size_t)b * SQ + q0 + prow) * SK + pseg;

    const int vrow = tid >> 3;              // 0..31
    const int vseg = (tid & 7) * 16;        // 0..112
    const __half* Vsrc = g_vf16 + ((size_t)b * SK + vrow) * DV + vseg;

    // smem store offsets (bytes)
    const uint32_t sAbase = (uint32_t)__cvta_generic_to_shared(&sA[0][0]);
    const uint32_t sBbase = (uint32_t)__cvta_generic_to_shared(&sB[0][0]);
    const uint32_t ABUF = 64 * AW * 2;
    const uint32_t BBUF = 32 * BW * 2;
    const uint32_t aSt = (uint32_t)((prow * AW + pseg) * 2);
    const uint32_t bSt = (uint32_t)((vrow * BW + vseg) * 2);

    // ldmatrix per-lane offsets
    const int g = lane >> 3, lr = lane & 7;
    const uint32_t aoff = (uint32_t)(((((g & 1) * 8 + lr) * AW) + (g >> 1) * 8) * 2);
    const uint32_t btoff = (uint32_t)((((g & 1) * 8 + lr) * BW + (warpN * 32 + (g >> 1) * 8)) * 2);

    float c[2][4][4];
#pragma unroll
    for (int i = 0; i < 2; i++)
#pragma unroll
        for (int j = 0; j < 4; j++)
#pragma unroll
            for (int r = 0; r < 4; r++) c[i][j][r] = 0.f;

    // prologue: chunk 0 -> buf 0
    cpa16(sAbase + aSt, Psrc);
    cpa16(sBbase + bSt, Vsrc);
    cpa16(sBbase + bSt + 16, Vsrc + 8);
    CP_COMMIT();

    int buf = 0;
#pragma unroll 1
    for (int chunk = 0; chunk < SK / 32; chunk++) {
        // issue chunk+1 into other buffer (overlaps this chunk's MMA)
        if (chunk < SK / 32 - 1) {
            uint32_t nb = (uint32_t)(buf ^ 1);
            const __half* ps = Psrc + (chunk + 1) * 32;
            const __half* vs = Vsrc + (size_t)(chunk + 1) * 32 * DV;
            cpa16(sAbase + nb * ABUF + aSt, ps);
            cpa16(sBbase + nb * BBUF + bSt, vs);
            cpa16(sBbase + nb * BBUF + bSt + 16, vs + 8);
            CP_COMMIT();
            CP_WAIT1();
        } else {
            CP_WAIT0();
        }
        __syncthreads();   // chunk's data visible to all warps

        // MMA: 2 k16 steps
#pragma unroll
        for (int ks = 0; ks < 2; ks++) {
            const uint32_t k0 = ks * 16;
            uint32_t bf[4][2];
#pragma unroll
            for (int jj = 0; jj < 2; jj++) {
                uint32_t badd = (uint32_t)buf * BBUF + k0 * BW * 2 + btoff + (uint32_t)(jj * 32);
                ldsm_x4_t(bf[2 * jj][0], bf[2 * jj][1], bf[2 * jj + 1][0], bf[2 * jj + 1][1],
                          sBbase + badd);
            }
#pragma unroll
            for (int i = 0; i < 2; i++) {
                uint32_t ar = (uint32_t)buf * ABUF +
                              (uint32_t)(((warpM * 32 + i * 16) * AW + k0) * 2) + aoff;
                uint32_t af[4];
                ldsm_x4(af[0], af[1], af[2], af[3], sAbase + ar);
#pragma unroll
                for (int j = 0; j < 4; j++)
                    mma_f16(c[i][j], af, bf[j][0], bf[j][1]);
            }
        }
        __syncthreads();   // drain: next iteration's cp.async may overwrite buf^1
        buf ^= 1;
    }

    // epilogue
#pragma unroll
    for (int i = 0; i < 2; i++) {
        int r1 = q0 + warpM * 32 + i * 16 + gid;
#pragma unroll
        for (int j = 0; j < 4; j++) {
            int col = warpN * 32 + j * 8 + tig * 2;
            float2 v0 = {c[i][j][0], c[i][j][1]};
            float2 v1 = {c[i][j][2], c[i][j][3]};
            *(float2*)&out[((size_t)b * SQ + r1) * DV + col] = v0;
            *(float2*)&out[((size_t)b * SQ + r1 + 8) * DV + col] = v1;
        }
    }
}

// ---------------------------------------------------------------------------
extern "C" void kernel_launch(void* const* d_in, const int* in_sizes, int n_in,
                              void* d_out, int out_size) {
    const float* Q = (const float*)d_in[0];   // [B,SQ,DQ]
    const float* K = (const float*)d_in[1];   // [B,SK,DK]
    const float* V = (const float*)d_in[2];   // [B,SK,DV]
    const float* W = (const float*)d_in[3];   // [DQ,DK]

    float* out  = (float*)d_out;                          // [B,SQ,DV]
    float* wout = (float*)d_out + (size_t)NB * SQ * DV;   // [B,SQ,SK]

    prep_v<<<NB * SK * DV / 2048, 256>>>(V);
    qw_kernel<<<NB * SQ / 64, 256>>>(Q, W);

    dim3 sg(SK / 128, SQ / 128, NB);
    score_kernel<<<sg, 256>>>(K, wout);

    softmax_kernel<<<NB * SQ, 256>>>(wout);

    dim3 pg(SQ / 64, NB);
    pv_kernel<<<pg, 256>>>(out);
}